// round 13
// baseline (speedup 1.0000x reference)
#include <cuda_runtime.h>
#include <cuda_bf16.h>
#include <cstdint>

#define N_NODES 16384
#define KNB 32
#define DIN 256
#define DOUT 256
#define DCAT 512
#define EPSBN 1e-5f

// ---------------- scratch (static __device__, no allocs) ----------------
__device__ float d_M[DIN * DIN];
__device__ float d_W2[DOUT * DOUT];
__device__ float d_bias12[DCAT];            // [tb | bio]
__device__ float d_b2[DOUT];
__device__ float d_v[DIN];
__device__ float d_c0[1];
__device__ float d_eb[N_NODES];
__device__ float d_ts[N_NODES * DIN];
__device__ float d_outcat[N_NODES * DCAT];
__device__ float d_part[128 * 1024];
__device__ float d_scale[DCAT];
__device__ float d_shift[DCAT];
// pre-split bf16 operands
__device__ __nv_bfloat16 d_B12h[DCAT * DIN], d_B12l[DCAT * DIN];   // [M;Wio]
__device__ __nv_bfloat16 d_B3h[DOUT * DIN],  d_B3l[DOUT * DIN];    // W2
__device__ __nv_bfloat16 d_B4h[DCAT * DCAT], d_B4l[DCAT * DCAT];   // Wg
__device__ __nv_bfloat16 d_xh[N_NODES * DIN],  d_xl[N_NODES * DIN];
__device__ __nv_bfloat16 d_ch[N_NODES * DIN],  d_cl[N_NODES * DIN];
__device__ __nv_bfloat16 d_och[N_NODES * DCAT], d_ocl[N_NODES * DCAT];

// ---------------- helpers ----------------
__device__ __forceinline__ uint32_t smem_u32(const void* p) {
    uint32_t a;
    asm("{ .reg .u64 t; cvta.to.shared.u64 t, %1; cvt.u32.u64 %0, t; }" : "=r"(a) : "l"(p));
    return a;
}
__device__ __forceinline__ void ldsm_x4(uint32_t addr, uint32_t& r0, uint32_t& r1,
                                        uint32_t& r2, uint32_t& r3) {
    asm volatile("ldmatrix.sync.aligned.m8n8.x4.shared.b16 {%0,%1,%2,%3}, [%4];"
                 : "=r"(r0), "=r"(r1), "=r"(r2), "=r"(r3) : "r"(addr));
}
__device__ __forceinline__ void mma16816(float* c, const uint32_t* a, const uint32_t* b) {
    asm volatile(
        "mma.sync.aligned.m16n8k16.row.col.f32.bf16.bf16.f32 "
        "{%0,%1,%2,%3}, {%4,%5,%6,%7}, {%8,%9}, {%0,%1,%2,%3};"
        : "+f"(c[0]), "+f"(c[1]), "+f"(c[2]), "+f"(c[3])
        : "r"(a[0]), "r"(a[1]), "r"(a[2]), "r"(a[3]), "r"(b[0]), "r"(b[1]));
}
__device__ __forceinline__ void cpa16(uint32_t saddr, const void* g) {
    asm volatile("cp.async.cg.shared.global [%0], [%1], 16;" :: "r"(saddr), "l"(g));
}
__device__ __forceinline__ void cpa_commit() {
    asm volatile("cp.async.commit_group;" ::: "memory");
}
template <int NP>
__device__ __forceinline__ void cpa_wait() {
    asm volatile("cp.async.wait_group %0;" :: "n"(NP) : "memory");
}
__device__ __forceinline__ uint32_t pack_bf16(__nv_bfloat16 lo, __nv_bfloat16 hi) {
    return ((uint32_t)__bfloat16_as_ushort(hi) << 16) | (uint32_t)__bfloat16_as_ushort(lo);
}
__device__ __forceinline__ void outstore(int row, int cc, float a, float b) {
    const size_t idx = (size_t)row * DCAT + cc;
    *(float2*)&d_outcat[idx] = make_float2(a, b);
    __nv_bfloat16 ha = __float2bfloat16(a), hb = __float2bfloat16(b);
    __nv_bfloat16 la = __float2bfloat16(a - __bfloat162float(ha));
    __nv_bfloat16 lb = __float2bfloat16(b - __bfloat162float(hb));
    *(uint32_t*)&d_och[idx] = pack_bf16(ha, hb);
    *(uint32_t*)&d_ocl[idx] = pack_bf16(la, lb);
}

// ---------------- K0: weight composition ----------------
__global__ void precompute_kernel(
    const float* __restrict__ Wq, const float* __restrict__ bq,
    const float* __restrict__ Wk, const float* __restrict__ bk,
    const float* __restrict__ Wv, const float* __restrict__ bv,
    const float* __restrict__ Wno, const float* __restrict__ bno,
    const float* __restrict__ bio)
{
    const int t = threadIdx.x;
    const int j = blockIdx.x;
    if (blockIdx.y == 0) {
        float acc = 0.f;
        #pragma unroll 4
        for (int o = 0; o < DOUT; o++) acc = fmaf(Wk[o * DIN + j], Wq[o * DIN + t], acc);
        d_M[j * DIN + t] = acc;
    } else if (blockIdx.y == 1) {
        float acc = 0.f;
        #pragma unroll 4
        for (int d = 0; d < DOUT; d++) acc = fmaf(Wno[j * DOUT + d], Wv[d * DIN + t], acc);
        d_W2[j * DOUT + t] = acc;
    } else if (blockIdx.x == 0) {
        float tb = 0.f, vv = 0.f, b2 = 0.f;
        for (int o = 0; o < DOUT; o++) {
            tb = fmaf(Wk[o * DIN + t], bq[o], tb);
            vv = fmaf(bk[o], Wq[o * DIN + t], vv);
        }
        for (int d = 0; d < DOUT; d++) b2 = fmaf(Wno[t * DOUT + d], bv[d], b2);
        d_bias12[t]       = tb;
        d_bias12[t + 256] = bio[t];
        d_v[t]  = vv;
        d_b2[t] = b2 + bno[t];
        if (t == 0) {
            float c = 0.f;
            for (int o = 0; o < DOUT; o++) c = fmaf(bk[o], bq[o], c);
            d_c0[0] = c;
        }
    }
}

// ---------------- K0b: split weights to bf16 hi/lo ----------------
__global__ void split_weights_kernel(const float* __restrict__ Wio,
                                     const float* __restrict__ Wg)
{
    const int t = threadIdx.x;
    const int row = blockIdx.x;
    if (blockIdx.y == 0) {
        float v = (row < 256) ? d_M[row * DIN + t] : Wio[(row - 256) * DIN + t];
        __nv_bfloat16 h = __float2bfloat16(v);
        d_B12h[row * DIN + t] = h;
        d_B12l[row * DIN + t] = __float2bfloat16(v - __bfloat162float(h));
    } else if (blockIdx.y == 1) {
        if (row < 256) {
            float v = d_W2[row * DIN + t];
            __nv_bfloat16 h = __float2bfloat16(v);
            d_B3h[row * DIN + t] = h;
            d_B3l[row * DIN + t] = __float2bfloat16(v - __bfloat162float(h));
        }
    } else {
        #pragma unroll
        for (int c = t; c < DCAT; c += 256) {
            float v = Wg[row * DCAT + c];
            __nv_bfloat16 h = __float2bfloat16(v);
            d_B4h[row * DCAT + c] = h;
            d_B4l[row * DCAT + c] = __float2bfloat16(v - __bfloat162float(h));
        }
    }
}

// ---------------- K0c: split x to bf16 hi/lo + ebias dot ----------------
__global__ __launch_bounds__(256) void split_x_kernel(const float* __restrict__ x)
{
    const int w = threadIdx.x >> 5, l = threadIdx.x & 31;
    const int n = blockIdx.x * 8 + w;
    float eb = 0.f;
    #pragma unroll
    for (int j = 0; j < 8; j++) {
        const int c = l + 32 * j;
        const float v = x[(size_t)n * DIN + c];
        __nv_bfloat16 h = __float2bfloat16(v);
        d_xh[(size_t)n * DIN + c] = h;
        d_xl[(size_t)n * DIN + c] = __float2bfloat16(v - __bfloat162float(h));
        eb = fmaf(v, d_v[c], eb);
    }
    #pragma unroll
    for (int off = 16; off > 0; off >>= 1) eb += __shfl_down_sync(0xffffffffu, eb, off);
    if (l == 0) d_eb[n] = eb + d_c0[0];
}

// ============ bf16-split tensor-core GEMM ============
// ASRC 1: A pre-split bf16 hi/lo (cp.async dbuf).
// MODE 0: G12 dual target; MODE 1: G3 -> outcat[:,256:512]; MODE 2: G4 gate -> Cout
template <int ASRC, int MODE>
__global__ __launch_bounds__(256, 2) void tc_gemm(
    const float* __restrict__ Afp,
    const __nv_bfloat16* __restrict__ Abh, const __nv_bfloat16* __restrict__ Abl,
    int lda,
    const __nv_bfloat16* __restrict__ Bh, const __nv_bfloat16* __restrict__ Bl,
    const float* __restrict__ bias, float* __restrict__ Cout, int Kdim)
{
    extern __shared__ char smem[];
    const uint32_t sb = smem_u32(smem);
    const int tid = threadIdx.x;
    const int wid = tid >> 5, lane = tid & 31;
    const int m0 = blockIdx.y * 128;
    const int n0 = blockIdx.x * 128;
    const int wm = (wid & 1) * 64;
    const int wn = (wid >> 1) * 32;

    float acc[4][4][4];
    #pragma unroll
    for (int i = 0; i < 4; i++)
        #pragma unroll
        for (int j = 0; j < 4; j++)
            #pragma unroll
            for (int q = 0; q < 4; q++) acc[i][j][q] = 0.f;

    const int r  = tid >> 1;          // 0..127
    const int h2 = tid & 1;

    auto issueB = [&](int kc, int buf) {
        const __nv_bfloat16* gh = Bh + (size_t)(n0 + r) * Kdim + kc + h2 * 16;
        const __nv_bfloat16* gl = Bl + (size_t)(n0 + r) * Kdim + kc + h2 * 16;
        const uint32_t d = sb + (uint32_t)(buf * 40960 + 20480) + r * 80 + h2 * 32;
        cpa16(d, gh);          cpa16(d + 16, gh + 8);
        cpa16(d + 10240, gl);  cpa16(d + 10240 + 16, gl + 8);
    };
    auto issueA = [&](int kc, int buf) {
        const __nv_bfloat16* gh = Abh + (size_t)(m0 + r) * lda + kc + h2 * 16;
        const __nv_bfloat16* gl = Abl + (size_t)(m0 + r) * lda + kc + h2 * 16;
        const uint32_t d = sb + (uint32_t)(buf * 40960) + r * 80 + h2 * 32;
        cpa16(d, gh);          cpa16(d + 16, gh + 8);
        cpa16(d + 10240, gl);  cpa16(d + 10240 + 16, gl + 8);
    };

    const int NC = Kdim >> 5;
    issueA(0, 0);
    issueB(0, 0);
    cpa_commit();

    for (int ic = 0; ic < NC; ic++) {
        const int buf = ic & 1;
        if (ic + 1 < NC) {
            issueA((ic + 1) << 5, buf ^ 1);
            issueB((ic + 1) << 5, buf ^ 1);
        }
        cpa_commit();
        cpa_wait<1>();
        __syncthreads();

        const uint32_t aH = sb + (uint32_t)(buf * 40960);
        const uint32_t aL = aH + 10240;
        const uint32_t bH = sb + (uint32_t)(buf * 40960 + 20480);
        const uint32_t bL = bH + 10240;

        #pragma unroll
        for (int kh2 = 0; kh2 < 2; kh2++) {
            uint32_t ah[4][4], al[4][4], bh[4][2], bl[4][2];
            const int cA = kh2 * 2 + ((lane >> 4) & 1);
            const int cB = kh2 * 2 + ((lane >> 3) & 1);
            #pragma unroll
            for (int mt = 0; mt < 4; mt++) {
                const int row = wm + mt * 16 + (lane & 15);
                ldsm_x4(aH + row * 80 + cA * 16,
                        ah[mt][0], ah[mt][1], ah[mt][2], ah[mt][3]);
            }
            #pragma unroll
            for (int p = 0; p < 2; p++) {
                const int row = wn + p * 16 + ((lane >> 4) & 1) * 8 + (lane & 7);
                uint32_t r0, r1, r2, r3;
                ldsm_x4(bH + row * 80 + cB * 16, r0, r1, r2, r3);
                bh[p * 2][0] = r0; bh[p * 2][1] = r1;
                bh[p * 2 + 1][0] = r2; bh[p * 2 + 1][1] = r3;
            }
            #pragma unroll
            for (int mt = 0; mt < 4; mt++) {
                const int row = wm + mt * 16 + (lane & 15);
                ldsm_x4(aL + row * 80 + cA * 16,
                        al[mt][0], al[mt][1], al[mt][2], al[mt][3]);
            }
            #pragma unroll
            for (int mt = 0; mt < 4; mt++)
                #pragma unroll
                for (int nt = 0; nt < 4; nt++)
                    mma16816(acc[mt][nt], ah[mt], bh[nt]);
            #pragma unroll
            for (int p = 0; p < 2; p++) {
                const int row = wn + p * 16 + ((lane >> 4) & 1) * 8 + (lane & 7);
                uint32_t r0, r1, r2, r3;
                ldsm_x4(bL + row * 80 + cB * 16, r0, r1, r2, r3);
                bl[p * 2][0] = r0; bl[p * 2][1] = r1;
                bl[p * 2 + 1][0] = r2; bl[p * 2 + 1][1] = r3;
            }
            #pragma unroll
            for (int mt = 0; mt < 4; mt++)
                #pragma unroll
                for (int nt = 0; nt < 4; nt++)
                    mma16816(acc[mt][nt], al[mt], bh[nt]);
            #pragma unroll
            for (int mt = 0; mt < 4; mt++)
                #pragma unroll
                for (int nt = 0; nt < 4; nt++)
                    mma16816(acc[mt][nt], ah[mt], bl[nt]);
        }
        __syncthreads();
    }

    // ---- epilogue ----
    #pragma unroll
    for (int mt = 0; mt < 4; mt++) {
        #pragma unroll
        for (int nt = 0; nt < 4; nt++) {
            const int col = n0 + wn + nt * 8 + (lane & 3) * 2;
            const int row0 = m0 + wm + mt * 16 + (lane >> 2);
            float2 bb = *(const float2*)(bias + col);
            const float v00 = acc[mt][nt][0] + bb.x;
            const float v01 = acc[mt][nt][1] + bb.y;
            const float v10 = acc[mt][nt][2] + bb.x;
            const float v11 = acc[mt][nt][3] + bb.y;
            if (MODE == 0) {
                if (col < 256) {
                    *(float2*)&d_ts[(size_t)row0 * DIN + col] = make_float2(v00, v01);
                    *(float2*)&d_ts[(size_t)(row0 + 8) * DIN + col] = make_float2(v10, v11);
                } else {
                    outstore(row0, col - 256, v00, v01);
                    outstore(row0 + 8, col - 256, v10, v11);
                }
            } else if (MODE == 1) {
                outstore(row0, col + 256, v00, v01);
                outstore(row0 + 8, col + 256, v10, v11);
            } else {
                float2 sc = *(const float2*)(d_scale + col);
                float2 sh = *(const float2*)(d_shift + col);
                float2 o0 = *(const float2*)&d_outcat[(size_t)row0 * DCAT + col];
                float2 o1 = *(const float2*)&d_outcat[(size_t)(row0 + 8) * DCAT + col];
                float2 w0, w1;
                w0.x = fmaxf(v00, 0.f) * fmaxf(fmaf(o0.x, sc.x, sh.x), 0.f);
                w0.y = fmaxf(v01, 0.f) * fmaxf(fmaf(o0.y, sc.y, sh.y), 0.f);
                w1.x = fmaxf(v10, 0.f) * fmaxf(fmaf(o1.x, sc.x, sh.x), 0.f);
                w1.y = fmaxf(v11, 0.f) * fmaxf(fmaf(o1.y, sc.y, sh.y), 0.f);
                *(float2*)(Cout + (size_t)row0 * DCAT + col) = w0;
                *(float2*)(Cout + (size_t)(row0 + 8) * DCAT + col) = w1;
            }
        }
    }
}

// ---------------- attention: per-warp row loads, eb precomputed ----------------
__global__ __launch_bounds__(256) void attn_kernel(const float* __restrict__ nb)
{
    __shared__ __align__(16) float Xs[KNB * DIN];   // 32 KB
    __shared__ float es[KNB], sx[KNB], att[KNB];

    const int n = blockIdx.x;
    const int t = threadIdx.x;
    const int w = t >> 5, l = t & 31;

    // each warp async-loads ITS OWN 4 rows (4KB): lane l takes chunks l+32j
    const uint32_t xsb = smem_u32(Xs);
    const char* src = (const char*)(nb + (size_t)n * KNB * DIN);
    #pragma unroll
    for (int j = 0; j < 8; j++) {
        const uint32_t idx = (uint32_t)(w * 256 + l + 32 * j);   // 16B chunk index
        cpa16(xsb + idx * 16, src + (size_t)idx * 16);
    }
    cpa_commit();

    // ts slice this lane needs
    float tsr[8];
    #pragma unroll
    for (int j = 0; j < 8; j++) tsr[j] = d_ts[(size_t)n * DIN + l + 32 * j];

    // wait only for this warp's own rows, then compute its energies
    cpa_wait<0>();
    __syncwarp();

    #pragma unroll
    for (int rr = 0; rr < 4; rr++) {
        const int k = 4 * w + rr;
        const float* xr = &Xs[k * DIN];
        float e = 0.f, s = 0.f;
        #pragma unroll
        for (int j = 0; j < 8; j++) {
            const float vx = xr[l + 32 * j];
            e = fmaf(vx, tsr[j], e);
            s += vx;
        }
        #pragma unroll
        for (int off = 16; off > 0; off >>= 1) {
            e += __shfl_down_sync(0xffffffffu, e, off);
            s += __shfl_down_sync(0xffffffffu, s, off);
        }
        if (l == 0) { es[k] = e; sx[k] = s; }
    }
    __syncthreads();

    if (w == 0) {
        const float s_eb = d_eb[n];
        float e = (sx[l] == 0.0f) ? 1e-12f : (es[l] + s_eb);
        float m = e;
        #pragma unroll
        for (int off = 16; off > 0; off >>= 1) m = fmaxf(m, __shfl_xor_sync(0xffffffffu, m, off));
        float p = __expf(e - m);
        float s = p;
        #pragma unroll
        for (int off = 16; off > 0; off >>= 1) s += __shfl_xor_sync(0xffffffffu, s, off);
        att[l] = p / s;
    }
    __syncthreads();

    float accv = 0.f;
    #pragma unroll
    for (int k = 0; k < KNB; k++) accv = fmaf(att[k], Xs[k * DIN + t], accv);

    __nv_bfloat16 h = __float2bfloat16(accv);
    d_ch[(size_t)n * DIN + t] = h;
    d_cl[(size_t)n * DIN + t] = __float2bfloat16(accv - __bfloat162float(h));
}

// ---------------- BN: deterministic two-pass ----------------
__global__ void bn_reduce_kernel()
{
    const int t = threadIdx.x;
    const int b = blockIdx.x;
    float s0 = 0.f, q0 = 0.f, s1 = 0.f, q1 = 0.f;
    for (int r = 0; r < 128; r++) {
        size_t row = (size_t)(b * 128 + r);
        float v0 = d_outcat[row * DCAT + t];
        float v1 = d_outcat[row * DCAT + t + 256];
        s0 += v0; q0 = fmaf(v0, v0, q0);
        s1 += v1; q1 = fmaf(v1, v1, q1);
    }
    d_part[b * 1024 + t]       = s0;
    d_part[b * 1024 + t + 256] = s1;
    d_part[b * 1024 + 512 + t]       = q0;
    d_part[b * 1024 + 512 + t + 256] = q1;
}

__global__ void bn_finalize_kernel(const float* __restrict__ gamma,
                                   const float* __restrict__ beta)
{
    const int c = blockIdx.x * 256 + threadIdx.x;
    float s = 0.f, q = 0.f;
    for (int p = 0; p < 128; p++) {
        s += d_part[p * 1024 + c];
        q += d_part[p * 1024 + 512 + c];
    }
    const float invN = 1.0f / (float)N_NODES;
    float mean = s * invN;
    float var  = q * invN - mean * mean;
    float inv  = rsqrtf(var + EPSBN);
    float scl  = gamma[c] * inv;
    d_scale[c] = scl;
    d_shift[c] = beta[c] - mean * scl;
}

// ---------------- launch ----------------
extern "C" void kernel_launch(void* const* d_in, const int* in_sizes, int n_in,
                              void* d_out, int out_size)
{
    const float* x    = (const float*)d_in[0];
    const float* nb   = (const float*)d_in[1];
    const float* Wq   = (const float*)d_in[2];
    const float* bq   = (const float*)d_in[3];
    const float* Wk   = (const float*)d_in[4];
    const float* bk   = (const float*)d_in[5];
    const float* Wv   = (const float*)d_in[6];
    const float* bv   = (const float*)d_in[7];
    const float* Wno  = (const float*)d_in[8];
    const float* bno  = (const float*)d_in[9];
    const float* Wio  = (const float*)d_in[10];
    const float* bio  = (const float*)d_in[11];
    const float* Wg   = (const float*)d_in[12];
    const float* bg   = (const float*)d_in[13];
    const float* gamma= (const float*)d_in[14];
    const float* beta = (const float*)d_in[15];
    float* out = (float*)d_out;

    void *pB12h, *pB12l, *pB3h, *pB3l, *pB4h, *pB4l;
    void *pxh, *pxl, *pch, *pcl, *poch, *pocl, *pbias12, *pb2;
    cudaGetSymbolAddress(&pB12h, d_B12h);
    cudaGetSymbolAddress(&pB12l, d_B12l);
    cudaGetSymbolAddress(&pB3h,  d_B3h);
    cudaGetSymbolAddress(&pB3l,  d_B3l);
    cudaGetSymbolAddress(&pB4h,  d_B4h);
    cudaGetSymbolAddress(&pB4l,  d_B4l);
    cudaGetSymbolAddress(&pxh,   d_xh);
    cudaGetSymbolAddress(&pxl,   d_xl);
    cudaGetSymbolAddress(&pch,   d_ch);
    cudaGetSymbolAddress(&pcl,   d_cl);
    cudaGetSymbolAddress(&poch,  d_och);
    cudaGetSymbolAddress(&pocl,  d_ocl);
    cudaGetSymbolAddress(&pbias12, d_bias12);
    cudaGetSymbolAddress(&pb2,     d_b2);

    cudaFuncSetAttribute(tc_gemm<1, 0>, cudaFuncAttributeMaxDynamicSharedMemorySize, 81920);
    cudaFuncSetAttribute(tc_gemm<1, 1>, cudaFuncAttributeMaxDynamicSharedMemorySize, 81920);
    cudaFuncSetAttribute(tc_gemm<1, 2>, cudaFuncAttributeMaxDynamicSharedMemorySize, 81920);

    precompute_kernel<<<dim3(256, 3), 256>>>(Wq, bq, Wk, bk, Wv, bv, Wno, bno, bio);
    split_weights_kernel<<<dim3(512, 3), 256>>>(Wio, Wg);
    split_x_kernel<<<N_NODES / 8, 256>>>(x);

    // G12: [ts | self_out] = x @ [M;Wio]^T + [tb|bio]   (pre-split A, full dbuf)
    tc_gemm<1, 0><<<dim3(4, 128), 256, 81920>>>(
        nullptr, (const __nv_bfloat16*)pxh, (const __nv_bfloat16*)pxl, DIN,
        (const __nv_bfloat16*)pB12h, (const __nv_bfloat16*)pB12l,
        (const float*)pbias12, nullptr, DIN);

    // attention -> c (bf16 hi/lo)
    attn_kernel<<<N_NODES, 256>>>(nb);

    // G3: neigh_out = c @ W2^T + b2 -> outcat[:,256:512]
    tc_gemm<1, 1><<<dim3(2, 128), 256, 81920>>>(
        nullptr, (const __nv_bfloat16*)pch, (const __nv_bfloat16*)pcl, DIN,
        (const __nv_bfloat16*)pB3h, (const __nv_bfloat16*)pB3l,
        (const float*)pb2, nullptr, DIN);

    bn_reduce_kernel<<<128, 256>>>();
    bn_finalize_kernel<<<2, 256>>>(gamma, beta);

    // G4: gate GEMM + fused BN/gate epilogue -> d_out
    tc_gemm<1, 2><<<dim3(4, 128), 256, 81920>>>(
        nullptr, (const __nv_bfloat16*)poch, (const __nv_bfloat16*)pocl, DCAT,
        (const __nv_bfloat16*)pB4h, (const __nv_bfloat16*)pB4l,
        bg, out, DCAT);
}

// round 15
// speedup vs baseline: 1.0275x; 1.0275x over previous
#include <cuda_runtime.h>
#include <cuda_bf16.h>
#include <cstdint>

#define N_NODES 16384
#define KNB 32
#define DIN 256
#define DOUT 256
#define DCAT 512
#define EPSBN 1e-5f

// ---------------- scratch (static __device__, no allocs) ----------------
__device__ float d_M[DIN * DIN];
__device__ float d_W2[DOUT * DOUT];
__device__ float d_bias12[DCAT];            // [tb | bio]
__device__ float d_b2[DOUT];
__device__ float d_v[DIN];
__device__ float d_c0[1];
__device__ float d_eb[N_NODES];
__device__ float d_ts[N_NODES * DIN];
__device__ float d_part[128 * 1024];
__device__ float d_scale[DCAT];
__device__ float d_shift[DCAT];
// pre-split bf16 operands
__device__ __nv_bfloat16 d_B12h[DCAT * DIN], d_B12l[DCAT * DIN];   // [M;Wio]
__device__ __nv_bfloat16 d_B3h[DOUT * DIN],  d_B3l[DOUT * DIN];    // W2
__device__ __nv_bfloat16 d_B4h[DCAT * DCAT], d_B4l[DCAT * DCAT];   // Wg
__device__ __nv_bfloat16 d_xh[N_NODES * DIN],  d_xl[N_NODES * DIN];
__device__ __nv_bfloat16 d_ch[N_NODES * DIN],  d_cl[N_NODES * DIN];
__device__ __nv_bfloat16 d_och[N_NODES * DCAT], d_ocl[N_NODES * DCAT];

// ---------------- helpers ----------------
__device__ __forceinline__ uint32_t smem_u32(const void* p) {
    uint32_t a;
    asm("{ .reg .u64 t; cvta.to.shared.u64 t, %1; cvt.u32.u64 %0, t; }" : "=r"(a) : "l"(p));
    return a;
}
__device__ __forceinline__ void ldsm_x4(uint32_t addr, uint32_t& r0, uint32_t& r1,
                                        uint32_t& r2, uint32_t& r3) {
    asm volatile("ldmatrix.sync.aligned.m8n8.x4.shared.b16 {%0,%1,%2,%3}, [%4];"
                 : "=r"(r0), "=r"(r1), "=r"(r2), "=r"(r3) : "r"(addr));
}
__device__ __forceinline__ void mma16816(float* c, const uint32_t* a, const uint32_t* b) {
    asm volatile(
        "mma.sync.aligned.m16n8k16.row.col.f32.bf16.bf16.f32 "
        "{%0,%1,%2,%3}, {%4,%5,%6,%7}, {%8,%9}, {%0,%1,%2,%3};"
        : "+f"(c[0]), "+f"(c[1]), "+f"(c[2]), "+f"(c[3])
        : "r"(a[0]), "r"(a[1]), "r"(a[2]), "r"(a[3]), "r"(b[0]), "r"(b[1]));
}
__device__ __forceinline__ void cpa16(uint32_t saddr, const void* g) {
    asm volatile("cp.async.cg.shared.global [%0], [%1], 16;" :: "r"(saddr), "l"(g));
}
__device__ __forceinline__ void cpa_commit() {
    asm volatile("cp.async.commit_group;" ::: "memory");
}
template <int NP>
__device__ __forceinline__ void cpa_wait() {
    asm volatile("cp.async.wait_group %0;" :: "n"(NP) : "memory");
}
__device__ __forceinline__ uint32_t pack_bf16(__nv_bfloat16 lo, __nv_bfloat16 hi) {
    return ((uint32_t)__bfloat16_as_ushort(hi) << 16) | (uint32_t)__bfloat16_as_ushort(lo);
}
// write bf16 hi/lo pair (fp32 value implied by hi+lo)
__device__ __forceinline__ void outstore(int row, int cc, float a, float b) {
    const size_t idx = (size_t)row * DCAT + cc;
    __nv_bfloat16 ha = __float2bfloat16(a), hb = __float2bfloat16(b);
    __nv_bfloat16 la = __float2bfloat16(a - __bfloat162float(ha));
    __nv_bfloat16 lb = __float2bfloat16(b - __bfloat162float(hb));
    *(uint32_t*)&d_och[idx] = pack_bf16(ha, hb);
    *(uint32_t*)&d_ocl[idx] = pack_bf16(la, lb);
}
// reconstruct fp32 pair from hi/lo bf16x2 words
__device__ __forceinline__ float2 rec2(size_t idx) {
    const uint32_t h = *(const uint32_t*)&d_och[idx];
    const uint32_t l = *(const uint32_t*)&d_ocl[idx];
    float2 r;
    r.x = __bfloat162float(__ushort_as_bfloat16((uint16_t)(h & 0xffff)))
        + __bfloat162float(__ushort_as_bfloat16((uint16_t)(l & 0xffff)));
    r.y = __bfloat162float(__ushort_as_bfloat16((uint16_t)(h >> 16)))
        + __bfloat162float(__ushort_as_bfloat16((uint16_t)(l >> 16)));
    return r;
}

// ---------------- K0: weight composition ----------------
__global__ void precompute_kernel(
    const float* __restrict__ Wq, const float* __restrict__ bq,
    const float* __restrict__ Wk, const float* __restrict__ bk,
    const float* __restrict__ Wv, const float* __restrict__ bv,
    const float* __restrict__ Wno, const float* __restrict__ bno,
    const float* __restrict__ bio)
{
    const int t = threadIdx.x;
    const int j = blockIdx.x;
    if (blockIdx.y == 0) {
        float acc = 0.f;
        #pragma unroll 4
        for (int o = 0; o < DOUT; o++) acc = fmaf(Wk[o * DIN + j], Wq[o * DIN + t], acc);
        d_M[j * DIN + t] = acc;
    } else if (blockIdx.y == 1) {
        float acc = 0.f;
        #pragma unroll 4
        for (int d = 0; d < DOUT; d++) acc = fmaf(Wno[j * DOUT + d], Wv[d * DIN + t], acc);
        d_W2[j * DOUT + t] = acc;
    } else if (blockIdx.x == 0) {
        float tb = 0.f, vv = 0.f, b2 = 0.f;
        for (int o = 0; o < DOUT; o++) {
            tb = fmaf(Wk[o * DIN + t], bq[o], tb);
            vv = fmaf(bk[o], Wq[o * DIN + t], vv);
        }
        for (int d = 0; d < DOUT; d++) b2 = fmaf(Wno[t * DOUT + d], bv[d], b2);
        d_bias12[t]       = tb;
        d_bias12[t + 256] = bio[t];
        d_v[t]  = vv;
        d_b2[t] = b2 + bno[t];
        if (t == 0) {
            float c = 0.f;
            for (int o = 0; o < DOUT; o++) c = fmaf(bk[o], bq[o], c);
            d_c0[0] = c;
        }
    }
}

// ---------------- K0b: split weights to bf16 hi/lo ----------------
__global__ void split_weights_kernel(const float* __restrict__ Wio,
                                     const float* __restrict__ Wg)
{
    const int t = threadIdx.x;
    const int row = blockIdx.x;
    if (blockIdx.y == 0) {
        float v = (row < 256) ? d_M[row * DIN + t] : Wio[(row - 256) * DIN + t];
        __nv_bfloat16 h = __float2bfloat16(v);
        d_B12h[row * DIN + t] = h;
        d_B12l[row * DIN + t] = __float2bfloat16(v - __bfloat162float(h));
    } else if (blockIdx.y == 1) {
        if (row < 256) {
            float v = d_W2[row * DIN + t];
            __nv_bfloat16 h = __float2bfloat16(v);
            d_B3h[row * DIN + t] = h;
            d_B3l[row * DIN + t] = __float2bfloat16(v - __bfloat162float(h));
        }
    } else {
        #pragma unroll
        for (int c = t; c < DCAT; c += 256) {
            float v = Wg[row * DCAT + c];
            __nv_bfloat16 h = __float2bfloat16(v);
            d_B4h[row * DCAT + c] = h;
            d_B4l[row * DCAT + c] = __float2bfloat16(v - __bfloat162float(h));
        }
    }
}

// ---------------- K0c: split x to bf16 hi/lo + ebias dot ----------------
__global__ __launch_bounds__(256) void split_x_kernel(const float* __restrict__ x)
{
    const int w = threadIdx.x >> 5, l = threadIdx.x & 31;
    const int n = blockIdx.x * 8 + w;
    float eb = 0.f;
    #pragma unroll
    for (int j = 0; j < 8; j++) {
        const int c = l + 32 * j;
        const float v = x[(size_t)n * DIN + c];
        __nv_bfloat16 h = __float2bfloat16(v);
        d_xh[(size_t)n * DIN + c] = h;
        d_xl[(size_t)n * DIN + c] = __float2bfloat16(v - __bfloat162float(h));
        eb = fmaf(v, d_v[c], eb);
    }
    #pragma unroll
    for (int off = 16; off > 0; off >>= 1) eb += __shfl_down_sync(0xffffffffu, eb, off);
    if (l == 0) d_eb[n] = eb + d_c0[0];
}

// ============ bf16-split tensor-core GEMM, 128x64 tile, 3 CTAs/SM ============
// A,B pre-split bf16 hi/lo. Smem rows 64B with XOR swizzle (chunk ^= (row>>1)&3).
// MODE 0: G12 dual target; MODE 1: G3 -> out[:,256:512]; MODE 2: G4 gate -> Cout
static constexpr int SM_AH = 0;
static constexpr int SM_AL = 8192;
static constexpr int SM_BH = 16384;
static constexpr int SM_BL = 20480;
static constexpr int SM_BUF = 24576;
static constexpr int SMEM_GEMM = 49152;

template <int MODE>
__global__ __launch_bounds__(256, 3) void tc_gemm(
    const __nv_bfloat16* __restrict__ Abh, const __nv_bfloat16* __restrict__ Abl,
    int lda,
    const __nv_bfloat16* __restrict__ Bh, const __nv_bfloat16* __restrict__ Bl,
    const float* __restrict__ bias, float* __restrict__ Cout, int Kdim)
{
    extern __shared__ char smem[];
    const uint32_t sb = smem_u32(smem);
    const int tid = threadIdx.x;
    const int wid = tid >> 5, lane = tid & 31;
    const int m0 = blockIdx.y * 128;
    const int n0 = blockIdx.x * 64;
    const int wm = (wid & 3) * 32;
    const int wn = (wid >> 2) * 32;

    float acc[2][4][4];
    #pragma unroll
    for (int i = 0; i < 2; i++)
        #pragma unroll
        for (int j = 0; j < 4; j++)
            #pragma unroll
            for (int q = 0; q < 4; q++) acc[i][j][q] = 0.f;

    const int r  = tid >> 1;          // 0..127
    const int h2 = tid & 1;
    const int swA = (r >> 1) & 3;
    const uint32_t pA0 = (uint32_t)(((2 * h2)     ^ swA) * 16);
    const uint32_t pA1 = (uint32_t)(((2 * h2 + 1) ^ swA) * 16);

    auto issueA = [&](int kc, int buf) {
        const __nv_bfloat16* gh = Abh + (size_t)(m0 + r) * lda + kc + h2 * 16;
        const __nv_bfloat16* gl = Abl + (size_t)(m0 + r) * lda + kc + h2 * 16;
        const uint32_t d = sb + (uint32_t)(buf * SM_BUF) + r * 64;
        cpa16(d + pA0, gh);            cpa16(d + pA1, gh + 8);
        cpa16(d + SM_AL + pA0, gl);    cpa16(d + SM_AL + pA1, gl + 8);
    };
    auto issueB = [&](int kc, int buf) {
        if (tid < 128) {
            const __nv_bfloat16* gh = Bh + (size_t)(n0 + r) * Kdim + kc + h2 * 16;
            const __nv_bfloat16* gl = Bl + (size_t)(n0 + r) * Kdim + kc + h2 * 16;
            const uint32_t d = sb + (uint32_t)(buf * SM_BUF) + SM_BH + r * 64;
            cpa16(d + pA0, gh);                        cpa16(d + pA1, gh + 8);
            cpa16(d + SM_BL - SM_BH + pA0, gl);        cpa16(d + SM_BL - SM_BH + pA1, gl + 8);
        }
    };

    const int NC = Kdim >> 5;
    issueA(0, 0);
    issueB(0, 0);
    cpa_commit();

    for (int ic = 0; ic < NC; ic++) {
        const int buf = ic & 1;
        if (ic + 1 < NC) {
            issueA((ic + 1) << 5, buf ^ 1);
            issueB((ic + 1) << 5, buf ^ 1);
        }
        cpa_commit();
        cpa_wait<1>();
        __syncthreads();

        const uint32_t aH = sb + (uint32_t)(buf * SM_BUF);
        const uint32_t aL = aH + SM_AL;
        const uint32_t bH = aH + SM_BH;
        const uint32_t bL = aH + SM_BL;

        #pragma unroll
        for (int kh2 = 0; kh2 < 2; kh2++) {
            uint32_t ah[2][4], al[2][4], bh[4][2], bl[4][2];
            const int cA = kh2 * 2 + ((lane >> 4) & 1);
            const int cB = kh2 * 2 + ((lane >> 3) & 1);
            #pragma unroll
            for (int mt = 0; mt < 2; mt++) {
                const int row = wm + mt * 16 + (lane & 15);
                const uint32_t off = row * 64 + ((cA ^ ((row >> 1) & 3)) * 16);
                ldsm_x4(aH + off, ah[mt][0], ah[mt][1], ah[mt][2], ah[mt][3]);
            }
            #pragma unroll
            for (int p = 0; p < 2; p++) {
                const int row = wn + p * 16 + ((lane >> 4) & 1) * 8 + (lane & 7);
                const uint32_t off = row * 64 + ((cB ^ ((row >> 1) & 3)) * 16);
                uint32_t r0, r1, r2, r3;
                ldsm_x4(bH + off, r0, r1, r2, r3);
                bh[p * 2][0] = r0; bh[p * 2][1] = r1;
                bh[p * 2 + 1][0] = r2; bh[p * 2 + 1][1] = r3;
            }
            #pragma unroll
            for (int mt = 0; mt < 2; mt++) {
                const int row = wm + mt * 16 + (lane & 15);
                const uint32_t off = row * 64 + ((cA ^ ((row >> 1) & 3)) * 16);
                ldsm_x4(aL + off, al[mt][0], al[mt][1], al[mt][2], al[mt][3]);
            }
            #pragma unroll
            for (int mt = 0; mt < 2; mt++)
                #pragma unroll
                for (int nt = 0; nt < 4; nt++)
                    mma16816(acc[mt][nt], ah[mt], bh[nt]);
            #pragma unroll
            for (int p = 0; p < 2; p++) {
                const int row = wn + p * 16 + ((lane >> 4) & 1) * 8 + (lane & 7);
                const uint32_t off = row * 64 + ((cB ^ ((row >> 1) & 3)) * 16);
                uint32_t r0, r1, r2, r3;
                ldsm_x4(bL + off, r0, r1, r2, r3);
                bl[p * 2][0] = r0; bl[p * 2][1] = r1;
                bl[p * 2 + 1][0] = r2; bl[p * 2 + 1][1] = r3;
            }
            #pragma unroll
            for (int mt = 0; mt < 2; mt++)
                #pragma unroll
                for (int nt = 0; nt < 4; nt++)
                    mma16816(acc[mt][nt], al[mt], bh[nt]);
            #pragma unroll
            for (int mt = 0; mt < 2; mt++)
                #pragma unroll
                for (int nt = 0; nt < 4; nt++)
                    mma16816(acc[mt][nt], ah[mt], bl[nt]);
        }
        __syncthreads();
    }

    // ---- epilogue ----
    #pragma unroll
    for (int mt = 0; mt < 2; mt++) {
        #pragma unroll
        for (int nt = 0; nt < 4; nt++) {
            const int col = n0 + wn + nt * 8 + (lane & 3) * 2;
            const int row0 = m0 + wm + mt * 16 + (lane >> 2);
            float2 bb = *(const float2*)(bias + col);
            const float v00 = acc[mt][nt][0] + bb.x;
            const float v01 = acc[mt][nt][1] + bb.y;
            const float v10 = acc[mt][nt][2] + bb.x;
            const float v11 = acc[mt][nt][3] + bb.y;
            if (MODE == 0) {
                if (col < 256) {
                    *(float2*)&d_ts[(size_t)row0 * DIN + col] = make_float2(v00, v01);
                    *(float2*)&d_ts[(size_t)(row0 + 8) * DIN + col] = make_float2(v10, v11);
                } else {
                    outstore(row0, col - 256, v00, v01);
                    outstore(row0 + 8, col - 256, v10, v11);
                }
            } else if (MODE == 1) {
                outstore(row0, col + 256, v00, v01);
                outstore(row0 + 8, col + 256, v10, v11);
            } else {
                float2 sc = *(const float2*)(d_scale + col);
                float2 sh = *(const float2*)(d_shift + col);
                float2 o0 = rec2((size_t)row0 * DCAT + col);
                float2 o1 = rec2((size_t)(row0 + 8) * DCAT + col);
                float2 w0, w1;
                w0.x = fmaxf(v00, 0.f) * fmaxf(fmaf(o0.x, sc.x, sh.x), 0.f);
                w0.y = fmaxf(v01, 0.f) * fmaxf(fmaf(o0.y, sc.y, sh.y), 0.f);
                w1.x = fmaxf(v10, 0.f) * fmaxf(fmaf(o1.x, sc.x, sh.x), 0.f);
                w1.y = fmaxf(v11, 0.f) * fmaxf(fmaf(o1.y, sc.y, sh.y), 0.f);
                *(float2*)(Cout + (size_t)row0 * DCAT + col) = w0;
                *(float2*)(Cout + (size_t)(row0 + 8) * DCAT + col) = w1;
            }
        }
    }
}

// ---------------- attention: per-warp row loads, eb precomputed ----------------
__global__ __launch_bounds__(256) void attn_kernel(const float* __restrict__ nb)
{
    __shared__ __align__(16) float Xs[KNB * DIN];   // 32 KB
    __shared__ float es[KNB], sx[KNB], att[KNB];

    const int n = blockIdx.x;
    const int t = threadIdx.x;
    const int w = t >> 5, l = t & 31;

    const uint32_t xsb = smem_u32(Xs);
    const char* src = (const char*)(nb + (size_t)n * KNB * DIN);
    #pragma unroll
    for (int j = 0; j < 8; j++) {
        const uint32_t idx = (uint32_t)(w * 256 + l + 32 * j);   // 16B chunk index
        cpa16(xsb + idx * 16, src + (size_t)idx * 16);
    }
    cpa_commit();

    float tsr[8];
    #pragma unroll
    for (int j = 0; j < 8; j++) tsr[j] = d_ts[(size_t)n * DIN + l + 32 * j];

    cpa_wait<0>();
    __syncwarp();

    #pragma unroll
    for (int rr = 0; rr < 4; rr++) {
        const int k = 4 * w + rr;
        const float* xr = &Xs[k * DIN];
        float e = 0.f, s = 0.f;
        #pragma unroll
        for (int j = 0; j < 8; j++) {
            const float vx = xr[l + 32 * j];
            e = fmaf(vx, tsr[j], e);
            s += vx;
        }
        #pragma unroll
        for (int off = 16; off > 0; off >>= 1) {
            e += __shfl_down_sync(0xffffffffu, e, off);
            s += __shfl_down_sync(0xffffffffu, s, off);
        }
        if (l == 0) { es[k] = e; sx[k] = s; }
    }
    __syncthreads();

    if (w == 0) {
        const float s_eb = d_eb[n];
        float e = (sx[l] == 0.0f) ? 1e-12f : (es[l] + s_eb);
        float m = e;
        #pragma unroll
        for (int off = 16; off > 0; off >>= 1) m = fmaxf(m, __shfl_xor_sync(0xffffffffu, m, off));
        float p = __expf(e - m);
        float s = p;
        #pragma unroll
        for (int off = 16; off > 0; off >>= 1) s += __shfl_xor_sync(0xffffffffu, s, off);
        att[l] = p / s;
    }
    __syncthreads();

    float accv = 0.f;
    #pragma unroll
    for (int k = 0; k < KNB; k++) accv = fmaf(att[k], Xs[k * DIN + t], accv);

    __nv_bfloat16 h = __float2bfloat16(accv);
    d_ch[(size_t)n * DIN + t] = h;
    d_cl[(size_t)n * DIN + t] = __float2bfloat16(accv - __bfloat162float(h));
}

// ---------------- BN: deterministic two-pass (reads bf16 hi/lo) ----------------
__global__ void bn_reduce_kernel()
{
    const int t = threadIdx.x;
    const int b = blockIdx.x;
    float s0 = 0.f, q0 = 0.f, s1 = 0.f, q1 = 0.f;
    for (int r = 0; r < 128; r++) {
        const size_t row = (size_t)(b * 128 + r);
        const size_t i0 = row * DCAT + t;
        const size_t i1 = i0 + 256;
        float v0 = __bfloat162float(d_och[i0]) + __bfloat162float(d_ocl[i0]);
        float v1 = __bfloat162float(d_och[i1]) + __bfloat162float(d_ocl[i1]);
        s0 += v0; q0 = fmaf(v0, v0, q0);
        s1 += v1; q1 = fmaf(v1, v1, q1);
    }
    d_part[b * 1024 + t]       = s0;
    d_part[b * 1024 + t + 256] = s1;
    d_part[b * 1024 + 512 + t]       = q0;
    d_part[b * 1024 + 512 + t + 256] = q1;
}

__global__ void bn_finalize_kernel(const float* __restrict__ gamma,
                                   const float* __restrict__ beta)
{
    const int c = blockIdx.x * 256 + threadIdx.x;
    float s = 0.f, q = 0.f;
    for (int p = 0; p < 128; p++) {
        s += d_part[p * 1024 + c];
        q += d_part[p * 1024 + 512 + c];
    }
    const float invN = 1.0f / (float)N_NODES;
    float mean = s * invN;
    float var  = q * invN - mean * mean;
    float inv  = rsqrtf(var + EPSBN);
    float scl  = gamma[c] * inv;
    d_scale[c] = scl;
    d_shift[c] = beta[c] - mean * scl;
}

// ---------------- launch ----------------
extern "C" void kernel_launch(void* const* d_in, const int* in_sizes, int n_in,
                              void* d_out, int out_size)
{
    const float* x    = (const float*)d_in[0];
    const float* nb   = (const float*)d_in[1];
    const float* Wq   = (const float*)d_in[2];
    const float* bq   = (const float*)d_in[3];
    const float* Wk   = (const float*)d_in[4];
    const float* bk   = (const float*)d_in[5];
    const float* Wv   = (const float*)d_in[6];
    const float* bv   = (const float*)d_in[7];
    const float* Wno  = (const float*)d_in[8];
    const float* bno  = (const float*)d_in[9];
    const float* Wio  = (const float*)d_in[10];
    const float* bio  = (const float*)d_in[11];
    const float* Wg   = (const float*)d_in[12];
    const float* bg   = (const float*)d_in[13];
    const float* gamma= (const float*)d_in[14];
    const float* beta = (const float*)d_in[15];
    float* out = (float*)d_out;

    void *pB12h, *pB12l, *pB3h, *pB3l, *pB4h, *pB4l;
    void *pxh, *pxl, *pch, *pcl, *poch, *pocl, *pbias12, *pb2;
    cudaGetSymbolAddress(&pB12h, d_B12h);
    cudaGetSymbolAddress(&pB12l, d_B12l);
    cudaGetSymbolAddress(&pB3h,  d_B3h);
    cudaGetSymbolAddress(&pB3l,  d_B3l);
    cudaGetSymbolAddress(&pB4h,  d_B4h);
    cudaGetSymbolAddress(&pB4l,  d_B4l);
    cudaGetSymbolAddress(&pxh,   d_xh);
    cudaGetSymbolAddress(&pxl,   d_xl);
    cudaGetSymbolAddress(&pch,   d_ch);
    cudaGetSymbolAddress(&pcl,   d_cl);
    cudaGetSymbolAddress(&poch,  d_och);
    cudaGetSymbolAddress(&pocl,  d_ocl);
    cudaGetSymbolAddress(&pbias12, d_bias12);
    cudaGetSymbolAddress(&pb2,     d_b2);

    cudaFuncSetAttribute(tc_gemm<0>, cudaFuncAttributeMaxDynamicSharedMemorySize, SMEM_GEMM);
    cudaFuncSetAttribute(tc_gemm<1>, cudaFuncAttributeMaxDynamicSharedMemorySize, SMEM_GEMM);
    cudaFuncSetAttribute(tc_gemm<2>, cudaFuncAttributeMaxDynamicSharedMemorySize, SMEM_GEMM);

    precompute_kernel<<<dim3(256, 3), 256>>>(Wq, bq, Wk, bk, Wv, bv, Wno, bno, bio);
    split_weights_kernel<<<dim3(512, 3), 256>>>(Wio, Wg);
    split_x_kernel<<<N_NODES / 8, 256>>>(x);

    // G12: [ts | self_out] = x @ [M;Wio]^T + [tb|bio]
    tc_gemm<0><<<dim3(8, 128), 256, SMEM_GEMM>>>(
        (const __nv_bfloat16*)pxh, (const __nv_bfloat16*)pxl, DIN,
        (const __nv_bfloat16*)pB12h, (const __nv_bfloat16*)pB12l,
        (const float*)pbias12, nullptr, DIN);

    // attention -> c (bf16 hi/lo)
    attn_kernel<<<N_NODES, 256>>>(nb);

    // G3: neigh_out = c @ W2^T + b2 -> out[:,256:512] (hi/lo)
    tc_gemm<1><<<dim3(4, 128), 256, SMEM_GEMM>>>(
        (const __nv_bfloat16*)pch, (const __nv_bfloat16*)pcl, DIN,
        (const __nv_bfloat16*)pB3h, (const __nv_bfloat16*)pB3l,
        (const float*)pb2, nullptr, DIN);

    bn_reduce_kernel<<<128, 256>>>();
    bn_finalize_kernel<<<2, 256>>>(gamma, beta);

    // G4: gate GEMM + fused BN/gate epilogue -> d_out
    tc_gemm<2><<<dim3(8, 128), 256, SMEM_GEMM>>>(
        (const __nv_bfloat16*)poch, (const __nv_bfloat16*)pocl, DCAT,
        (const __nv_bfloat16*)pB4h, (const __nv_bfloat16*)pB4l,
        bg, out, DCAT);
}

// round 17
// speedup vs baseline: 1.0576x; 1.0293x over previous
#include <cuda_runtime.h>
#include <cuda_bf16.h>
#include <cstdint>

#define N_NODES 16384
#define KNB 32
#define DIN 256
#define DOUT 256
#define DCAT 512
#define EPSBN 1e-5f

// ---------------- scratch (static __device__, no allocs) ----------------
__device__ float d_M[DIN * DIN];
__device__ float d_W2[DOUT * DOUT];
__device__ float d_bias12[DCAT];            // [tb | bio]
__device__ float d_b2[DOUT];
__device__ float d_v[DIN];
__device__ float d_c0[1];
__device__ float d_eb[N_NODES];
__device__ float d_ts[N_NODES * DIN];
__device__ float d_part[128 * 1024];
__device__ float d_scale[DCAT];
__device__ float d_shift[DCAT];
// pre-split bf16 operands
__device__ __nv_bfloat16 d_B12h[DCAT * DIN], d_B12l[DCAT * DIN];   // [M;Wio]
__device__ __nv_bfloat16 d_B3h[DOUT * DIN],  d_B3l[DOUT * DIN];    // W2
__device__ __nv_bfloat16 d_B4h[DCAT * DCAT], d_B4l[DCAT * DCAT];   // Wg
__device__ __nv_bfloat16 d_xh[N_NODES * DIN],  d_xl[N_NODES * DIN];
__device__ __nv_bfloat16 d_ch[N_NODES * DIN],  d_cl[N_NODES * DIN];
__device__ __nv_bfloat16 d_och[N_NODES * DCAT], d_ocl[N_NODES * DCAT];

// ---------------- helpers ----------------
__device__ __forceinline__ uint32_t smem_u32(const void* p) {
    uint32_t a;
    asm("{ .reg .u64 t; cvta.to.shared.u64 t, %1; cvt.u32.u64 %0, t; }" : "=r"(a) : "l"(p));
    return a;
}
__device__ __forceinline__ void ldsm_x4(uint32_t addr, uint32_t& r0, uint32_t& r1,
                                        uint32_t& r2, uint32_t& r3) {
    asm volatile("ldmatrix.sync.aligned.m8n8.x4.shared.b16 {%0,%1,%2,%3}, [%4];"
                 : "=r"(r0), "=r"(r1), "=r"(r2), "=r"(r3) : "r"(addr));
}
__device__ __forceinline__ void mma16816(float* c, const uint32_t* a, const uint32_t* b) {
    asm volatile(
        "mma.sync.aligned.m16n8k16.row.col.f32.bf16.bf16.f32 "
        "{%0,%1,%2,%3}, {%4,%5,%6,%7}, {%8,%9}, {%0,%1,%2,%3};"
        : "+f"(c[0]), "+f"(c[1]), "+f"(c[2]), "+f"(c[3])
        : "r"(a[0]), "r"(a[1]), "r"(a[2]), "r"(a[3]), "r"(b[0]), "r"(b[1]));
}
__device__ __forceinline__ void cpa16(uint32_t saddr, const void* g) {
    asm volatile("cp.async.cg.shared.global [%0], [%1], 16;" :: "r"(saddr), "l"(g));
}
__device__ __forceinline__ void cpa_commit() {
    asm volatile("cp.async.commit_group;" ::: "memory");
}
template <int NP>
__device__ __forceinline__ void cpa_wait() {
    asm volatile("cp.async.wait_group %0;" :: "n"(NP) : "memory");
}
__device__ __forceinline__ uint32_t pack_bf16(__nv_bfloat16 lo, __nv_bfloat16 hi) {
    return ((uint32_t)__bfloat16_as_ushort(hi) << 16) | (uint32_t)__bfloat16_as_ushort(lo);
}
// write bf16 hi/lo pair (fp32 value implied by hi+lo)
__device__ __forceinline__ void outstore(int row, int cc, float a, float b) {
    const size_t idx = (size_t)row * DCAT + cc;
    __nv_bfloat16 ha = __float2bfloat16(a), hb = __float2bfloat16(b);
    __nv_bfloat16 la = __float2bfloat16(a - __bfloat162float(ha));
    __nv_bfloat16 lb = __float2bfloat16(b - __bfloat162float(hb));
    *(uint32_t*)&d_och[idx] = pack_bf16(ha, hb);
    *(uint32_t*)&d_ocl[idx] = pack_bf16(la, lb);
}
// reconstruct fp32 pair from hi/lo bf16x2 words
__device__ __forceinline__ float2 rec2(size_t idx) {
    const uint32_t h = *(const uint32_t*)&d_och[idx];
    const uint32_t l = *(const uint32_t*)&d_ocl[idx];
    float2 r;
    r.x = __bfloat162float(__ushort_as_bfloat16((uint16_t)(h & 0xffff)))
        + __bfloat162float(__ushort_as_bfloat16((uint16_t)(l & 0xffff)));
    r.y = __bfloat162float(__ushort_as_bfloat16((uint16_t)(h >> 16)))
        + __bfloat162float(__ushort_as_bfloat16((uint16_t)(l >> 16)));
    return r;
}

// ---------------- K0: weight composition ----------------
__global__ void precompute_kernel(
    const float* __restrict__ Wq, const float* __restrict__ bq,
    const float* __restrict__ Wk, const float* __restrict__ bk,
    const float* __restrict__ Wv, const float* __restrict__ bv,
    const float* __restrict__ Wno, const float* __restrict__ bno,
    const float* __restrict__ bio)
{
    const int t = threadIdx.x;
    const int j = blockIdx.x;
    if (blockIdx.y == 0) {
        float acc = 0.f;
        #pragma unroll 4
        for (int o = 0; o < DOUT; o++) acc = fmaf(Wk[o * DIN + j], Wq[o * DIN + t], acc);
        d_M[j * DIN + t] = acc;
    } else if (blockIdx.y == 1) {
        float acc = 0.f;
        #pragma unroll 4
        for (int d = 0; d < DOUT; d++) acc = fmaf(Wno[j * DOUT + d], Wv[d * DIN + t], acc);
        d_W2[j * DOUT + t] = acc;
    } else if (blockIdx.x == 0) {
        float tb = 0.f, vv = 0.f, b2 = 0.f;
        for (int o = 0; o < DOUT; o++) {
            tb = fmaf(Wk[o * DIN + t], bq[o], tb);
            vv = fmaf(bk[o], Wq[o * DIN + t], vv);
        }
        for (int d = 0; d < DOUT; d++) b2 = fmaf(Wno[t * DOUT + d], bv[d], b2);
        d_bias12[t]       = tb;
        d_bias12[t + 256] = bio[t];
        d_v[t]  = vv;
        d_b2[t] = b2 + bno[t];
        if (t == 0) {
            float c = 0.f;
            for (int o = 0; o < DOUT; o++) c = fmaf(bk[o], bq[o], c);
            d_c0[0] = c;
        }
    }
}

// ---------------- K0b: split weights to bf16 hi/lo ----------------
__global__ void split_weights_kernel(const float* __restrict__ Wio,
                                     const float* __restrict__ Wg)
{
    const int t = threadIdx.x;
    const int row = blockIdx.x;
    if (blockIdx.y == 0) {
        float v = (row < 256) ? d_M[row * DIN + t] : Wio[(row - 256) * DIN + t];
        __nv_bfloat16 h = __float2bfloat16(v);
        d_B12h[row * DIN + t] = h;
        d_B12l[row * DIN + t] = __float2bfloat16(v - __bfloat162float(h));
    } else if (blockIdx.y == 1) {
        if (row < 256) {
            float v = d_W2[row * DIN + t];
            __nv_bfloat16 h = __float2bfloat16(v);
            d_B3h[row * DIN + t] = h;
            d_B3l[row * DIN + t] = __float2bfloat16(v - __bfloat162float(h));
        }
    } else {
        #pragma unroll
        for (int c = t; c < DCAT; c += 256) {
            float v = Wg[row * DCAT + c];
            __nv_bfloat16 h = __float2bfloat16(v);
            d_B4h[row * DCAT + c] = h;
            d_B4l[row * DCAT + c] = __float2bfloat16(v - __bfloat162float(h));
        }
    }
}

// ---------------- K0c: split x to bf16 hi/lo + ebias dot ----------------
__global__ __launch_bounds__(256) void split_x_kernel(const float* __restrict__ x)
{
    const int w = threadIdx.x >> 5, l = threadIdx.x & 31;
    const int n = blockIdx.x * 8 + w;
    float eb = 0.f;
    #pragma unroll
    for (int j = 0; j < 8; j++) {
        const int c = l + 32 * j;
        const float v = x[(size_t)n * DIN + c];
        __nv_bfloat16 h = __float2bfloat16(v);
        d_xh[(size_t)n * DIN + c] = h;
        d_xl[(size_t)n * DIN + c] = __float2bfloat16(v - __bfloat162float(h));
        eb = fmaf(v, d_v[c], eb);
    }
    #pragma unroll
    for (int off = 16; off > 0; off >>= 1) eb += __shfl_down_sync(0xffffffffu, eb, off);
    if (l == 0) d_eb[n] = eb + d_c0[0];
}

// ============ bf16-split tensor-core GEMM, 128x64 tile, 3 CTAs/SM ============
// A,B pre-split bf16 hi/lo. Smem rows 64B with XOR swizzle (chunk ^= (row>>1)&3).
// MODE 0: write d_ts; MODE 1: outstore at col+colOff; MODE 2: G4 gate -> Cout
static constexpr int SM_AL = 8192;
static constexpr int SM_BH = 16384;
static constexpr int SM_BL = 20480;
static constexpr int SM_BUF = 24576;
static constexpr int SMEM_GEMM = 49152;

template <int MODE>
__global__ __launch_bounds__(256, 3) void tc_gemm(
    const __nv_bfloat16* __restrict__ Abh, const __nv_bfloat16* __restrict__ Abl,
    int lda,
    const __nv_bfloat16* __restrict__ Bh, const __nv_bfloat16* __restrict__ Bl,
    const float* __restrict__ bias, float* __restrict__ Cout, int Kdim, int colOff)
{
    extern __shared__ char smem[];
    const uint32_t sb = smem_u32(smem);
    const int tid = threadIdx.x;
    const int wid = tid >> 5, lane = tid & 31;
    const int m0 = blockIdx.y * 128;
    const int n0 = blockIdx.x * 64;
    const int wm = (wid & 3) * 32;
    const int wn = (wid >> 2) * 32;

    float acc[2][4][4];
    #pragma unroll
    for (int i = 0; i < 2; i++)
        #pragma unroll
        for (int j = 0; j < 4; j++)
            #pragma unroll
            for (int q = 0; q < 4; q++) acc[i][j][q] = 0.f;

    const int r  = tid >> 1;          // 0..127
    const int h2 = tid & 1;
    const int swA = (r >> 1) & 3;
    const uint32_t pA0 = (uint32_t)(((2 * h2)     ^ swA) * 16);
    const uint32_t pA1 = (uint32_t)(((2 * h2 + 1) ^ swA) * 16);

    auto issueA = [&](int kc, int buf) {
        const __nv_bfloat16* gh = Abh + (size_t)(m0 + r) * lda + kc + h2 * 16;
        const __nv_bfloat16* gl = Abl + (size_t)(m0 + r) * lda + kc + h2 * 16;
        const uint32_t d = sb + (uint32_t)(buf * SM_BUF) + r * 64;
        cpa16(d + pA0, gh);            cpa16(d + pA1, gh + 8);
        cpa16(d + SM_AL + pA0, gl);    cpa16(d + SM_AL + pA1, gl + 8);
    };
    auto issueB = [&](int kc, int buf) {
        if (tid < 128) {
            const __nv_bfloat16* gh = Bh + (size_t)(n0 + r) * Kdim + kc + h2 * 16;
            const __nv_bfloat16* gl = Bl + (size_t)(n0 + r) * Kdim + kc + h2 * 16;
            const uint32_t d = sb + (uint32_t)(buf * SM_BUF) + SM_BH + r * 64;
            cpa16(d + pA0, gh);                        cpa16(d + pA1, gh + 8);
            cpa16(d + SM_BL - SM_BH + pA0, gl);        cpa16(d + SM_BL - SM_BH + pA1, gl + 8);
        }
    };

    const int NC = Kdim >> 5;
    issueA(0, 0);
    issueB(0, 0);
    cpa_commit();

    for (int ic = 0; ic < NC; ic++) {
        const int buf = ic & 1;
        if (ic + 1 < NC) {
            issueA((ic + 1) << 5, buf ^ 1);
            issueB((ic + 1) << 5, buf ^ 1);
        }
        cpa_commit();
        cpa_wait<1>();
        __syncthreads();

        const uint32_t aH = sb + (uint32_t)(buf * SM_BUF);
        const uint32_t aL = aH + SM_AL;
        const uint32_t bH = aH + SM_BH;
        const uint32_t bL = aH + SM_BL;

        #pragma unroll
        for (int kh2 = 0; kh2 < 2; kh2++) {
            uint32_t ah[2][4], al[2][4], bh[4][2], bl[4][2];
            const int cA = kh2 * 2 + ((lane >> 4) & 1);
            const int cB = kh2 * 2 + ((lane >> 3) & 1);
            #pragma unroll
            for (int mt = 0; mt < 2; mt++) {
                const int row = wm + mt * 16 + (lane & 15);
                const uint32_t off = row * 64 + ((cA ^ ((row >> 1) & 3)) * 16);
                ldsm_x4(aH + off, ah[mt][0], ah[mt][1], ah[mt][2], ah[mt][3]);
            }
            #pragma unroll
            for (int p = 0; p < 2; p++) {
                const int row = wn + p * 16 + ((lane >> 4) & 1) * 8 + (lane & 7);
                const uint32_t off = row * 64 + ((cB ^ ((row >> 1) & 3)) * 16);
                uint32_t r0, r1, r2, r3;
                ldsm_x4(bH + off, r0, r1, r2, r3);
                bh[p * 2][0] = r0; bh[p * 2][1] = r1;
                bh[p * 2 + 1][0] = r2; bh[p * 2 + 1][1] = r3;
            }
            #pragma unroll
            for (int mt = 0; mt < 2; mt++) {
                const int row = wm + mt * 16 + (lane & 15);
                const uint32_t off = row * 64 + ((cA ^ ((row >> 1) & 3)) * 16);
                ldsm_x4(aL + off, al[mt][0], al[mt][1], al[mt][2], al[mt][3]);
            }
            #pragma unroll
            for (int mt = 0; mt < 2; mt++)
                #pragma unroll
                for (int nt = 0; nt < 4; nt++)
                    mma16816(acc[mt][nt], ah[mt], bh[nt]);
            #pragma unroll
            for (int p = 0; p < 2; p++) {
                const int row = wn + p * 16 + ((lane >> 4) & 1) * 8 + (lane & 7);
                const uint32_t off = row * 64 + ((cB ^ ((row >> 1) & 3)) * 16);
                uint32_t r0, r1, r2, r3;
                ldsm_x4(bL + off, r0, r1, r2, r3);
                bl[p * 2][0] = r0; bl[p * 2][1] = r1;
                bl[p * 2 + 1][0] = r2; bl[p * 2 + 1][1] = r3;
            }
            #pragma unroll
            for (int mt = 0; mt < 2; mt++)
                #pragma unroll
                for (int nt = 0; nt < 4; nt++)
                    mma16816(acc[mt][nt], al[mt], bh[nt]);
            #pragma unroll
            for (int mt = 0; mt < 2; mt++)
                #pragma unroll
                for (int nt = 0; nt < 4; nt++)
                    mma16816(acc[mt][nt], ah[mt], bl[nt]);
        }
        __syncthreads();
    }

    // ---- epilogue ----
    #pragma unroll
    for (int mt = 0; mt < 2; mt++) {
        #pragma unroll
        for (int nt = 0; nt < 4; nt++) {
            const int col = n0 + wn + nt * 8 + (lane & 3) * 2;
            const int row0 = m0 + wm + mt * 16 + (lane >> 2);
            float2 bb = *(const float2*)(bias + col);
            const float v00 = acc[mt][nt][0] + bb.x;
            const float v01 = acc[mt][nt][1] + bb.y;
            const float v10 = acc[mt][nt][2] + bb.x;
            const float v11 = acc[mt][nt][3] + bb.y;
            if (MODE == 0) {
                *(float2*)&d_ts[(size_t)row0 * DIN + col] = make_float2(v00, v01);
                *(float2*)&d_ts[(size_t)(row0 + 8) * DIN + col] = make_float2(v10, v11);
            } else if (MODE == 1) {
                outstore(row0, col + colOff, v00, v01);
                outstore(row0 + 8, col + colOff, v10, v11);
            } else {
                float2 sc = *(const float2*)(d_scale + col);
                float2 sh = *(const float2*)(d_shift + col);
                float2 o0 = rec2((size_t)row0 * DCAT + col);
                float2 o1 = rec2((size_t)(row0 + 8) * DCAT + col);
                float2 w0, w1;
                w0.x = fmaxf(v00, 0.f) * fmaxf(fmaf(o0.x, sc.x, sh.x), 0.f);
                w0.y = fmaxf(v01, 0.f) * fmaxf(fmaf(o0.y, sc.y, sh.y), 0.f);
                w1.x = fmaxf(v10, 0.f) * fmaxf(fmaf(o1.x, sc.x, sh.x), 0.f);
                w1.y = fmaxf(v11, 0.f) * fmaxf(fmaf(o1.y, sc.y, sh.y), 0.f);
                *(float2*)(Cout + (size_t)row0 * DCAT + col) = w0;
                *(float2*)(Cout + (size_t)(row0 + 8) * DCAT + col) = w1;
            }
        }
    }
}

// ---------------- attention: per-warp row loads, eb precomputed ----------------
__global__ __launch_bounds__(256) void attn_kernel(const float* __restrict__ nb)
{
    __shared__ __align__(16) float Xs[KNB * DIN];   // 32 KB
    __shared__ float es[KNB], sx[KNB], att[KNB];

    const int n = blockIdx.x;
    const int t = threadIdx.x;
    const int w = t >> 5, l = t & 31;

    const uint32_t xsb = smem_u32(Xs);
    const char* src = (const char*)(nb + (size_t)n * KNB * DIN);
    #pragma unroll
    for (int j = 0; j < 8; j++) {
        const uint32_t idx = (uint32_t)(w * 256 + l + 32 * j);   // 16B chunk index
        cpa16(xsb + idx * 16, src + (size_t)idx * 16);
    }
    cpa_commit();

    float tsr[8];
    #pragma unroll
    for (int j = 0; j < 8; j++) tsr[j] = d_ts[(size_t)n * DIN + l + 32 * j];

    cpa_wait<0>();
    __syncwarp();

    #pragma unroll
    for (int rr = 0; rr < 4; rr++) {
        const int k = 4 * w + rr;
        const float* xr = &Xs[k * DIN];
        float e = 0.f, s = 0.f;
        #pragma unroll
        for (int j = 0; j < 8; j++) {
            const float vx = xr[l + 32 * j];
            e = fmaf(vx, tsr[j], e);
            s += vx;
        }
        #pragma unroll
        for (int off = 16; off > 0; off >>= 1) {
            e += __shfl_down_sync(0xffffffffu, e, off);
            s += __shfl_down_sync(0xffffffffu, s, off);
        }
        if (l == 0) { es[k] = e; sx[k] = s; }
    }
    __syncthreads();

    if (w == 0) {
        const float s_eb = d_eb[n];
        float e = (sx[l] == 0.0f) ? 1e-12f : (es[l] + s_eb);
        float m = e;
        #pragma unroll
        for (int off = 16; off > 0; off >>= 1) m = fmaxf(m, __shfl_xor_sync(0xffffffffu, m, off));
        float p = __expf(e - m);
        float s = p;
        #pragma unroll
        for (int off = 16; off > 0; off >>= 1) s += __shfl_xor_sync(0xffffffffu, s, off);
        att[l] = p / s;
    }
    __syncthreads();

    float accv = 0.f;
    #pragma unroll
    for (int k = 0; k < KNB; k++) accv = fmaf(att[k], Xs[k * DIN + t], accv);

    __nv_bfloat16 h = __float2bfloat16(accv);
    d_ch[(size_t)n * DIN + t] = h;
    d_cl[(size_t)n * DIN + t] = __float2bfloat16(accv - __bfloat162float(h));
}

// ---------------- BN: deterministic two-pass, split by column half ----------------
template <int HALF>
__global__ void bn_reduce_kernel()
{
    const int t = threadIdx.x;
    const int b = blockIdx.x;
    const int c = HALF * 256 + t;
    float s0 = 0.f, q0 = 0.f;
    for (int r = 0; r < 128; r++) {
        const size_t idx = (size_t)(b * 128 + r) * DCAT + c;
        float v = __bfloat162float(d_och[idx]) + __bfloat162float(d_ocl[idx]);
        s0 += v; q0 = fmaf(v, v, q0);
    }
    d_part[b * 1024 + c]       = s0;
    d_part[b * 1024 + 512 + c] = q0;
}

__global__ void bn_finalize_kernel(const float* __restrict__ gamma,
                                   const float* __restrict__ beta)
{
    const int c = blockIdx.x * 256 + threadIdx.x;
    float s = 0.f, q = 0.f;
    for (int p = 0; p < 128; p++) {
        s += d_part[p * 1024 + c];
        q += d_part[p * 1024 + 512 + c];
    }
    const float invN = 1.0f / (float)N_NODES;
    float mean = s * invN;
    float var  = q * invN - mean * mean;
    float inv  = rsqrtf(var + EPSBN);
    float scl  = gamma[c] * inv;
    d_scale[c] = scl;
    d_shift[c] = beta[c] - mean * scl;
}

// ---------------- launch ----------------
extern "C" void kernel_launch(void* const* d_in, const int* in_sizes, int n_in,
                              void* d_out, int out_size)
{
    const float* x    = (const float*)d_in[0];
    const float* nb   = (const float*)d_in[1];
    const float* Wq   = (const float*)d_in[2];
    const float* bq   = (const float*)d_in[3];
    const float* Wk   = (const float*)d_in[4];
    const float* bk   = (const float*)d_in[5];
    const float* Wv   = (const float*)d_in[6];
    const float* bv   = (const float*)d_in[7];
    const float* Wno  = (const float*)d_in[8];
    const float* bno  = (const float*)d_in[9];
    const float* Wio  = (const float*)d_in[10];
    const float* bio  = (const float*)d_in[11];
    const float* Wg   = (const float*)d_in[12];
    const float* bg   = (const float*)d_in[13];
    const float* gamma= (const float*)d_in[14];
    const float* beta = (const float*)d_in[15];
    float* out = (float*)d_out;

    void *pB12h, *pB12l, *pB3h, *pB3l, *pB4h, *pB4l;
    void *pxh, *pxl, *pch, *pcl, *poch, *pocl, *pbias12, *pb2;
    cudaGetSymbolAddress(&pB12h, d_B12h);
    cudaGetSymbolAddress(&pB12l, d_B12l);
    cudaGetSymbolAddress(&pB3h,  d_B3h);
    cudaGetSymbolAddress(&pB3l,  d_B3l);
    cudaGetSymbolAddress(&pB4h,  d_B4h);
    cudaGetSymbolAddress(&pB4l,  d_B4l);
    cudaGetSymbolAddress(&pxh,   d_xh);
    cudaGetSymbolAddress(&pxl,   d_xl);
    cudaGetSymbolAddress(&pch,   d_ch);
    cudaGetSymbolAddress(&pcl,   d_cl);
    cudaGetSymbolAddress(&poch,  d_och);
    cudaGetSymbolAddress(&pocl,  d_ocl);
    cudaGetSymbolAddress(&pbias12, d_bias12);
    cudaGetSymbolAddress(&pb2,     d_b2);

    cudaFuncSetAttribute(tc_gemm<0>, cudaFuncAttributeMaxDynamicSharedMemorySize, SMEM_GEMM);
    cudaFuncSetAttribute(tc_gemm<1>, cudaFuncAttributeMaxDynamicSharedMemorySize, SMEM_GEMM);
    cudaFuncSetAttribute(tc_gemm<2>, cudaFuncAttributeMaxDynamicSharedMemorySize, SMEM_GEMM);

    // side stream + fork/join events (created per call; capture-safe, no device mem)
    cudaStream_t s2;
    cudaStreamCreateWithFlags(&s2, cudaStreamNonBlocking);
    cudaEvent_t e1, e2;
    cudaEventCreateWithFlags(&e1, cudaEventDisableTiming);
    cudaEventCreateWithFlags(&e2, cudaEventDisableTiming);

    // ---- main stream: prep ----
    precompute_kernel<<<dim3(256, 3), 256>>>(Wq, bq, Wk, bk, Wv, bv, Wno, bno, bio);
    split_weights_kernel<<<dim3(512, 3), 256>>>(Wio, Wg);
    split_x_kernel<<<N_NODES / 8, 256>>>(x);

    // ---- fork: G2 (self_out) + bn half 0 on side stream ----
    cudaEventRecord(e1, 0);
    cudaStreamWaitEvent(s2, e1, 0);
    tc_gemm<1><<<dim3(4, 128), 256, SMEM_GEMM, s2>>>(
        (const __nv_bfloat16*)pxh, (const __nv_bfloat16*)pxl, DIN,
        (const __nv_bfloat16*)pB12h + 256 * DIN, (const __nv_bfloat16*)pB12l + 256 * DIN,
        (const float*)pbias12 + 256, nullptr, DIN, 0);
    bn_reduce_kernel<0><<<128, 256, 0, s2>>>();
    cudaEventRecord(e2, s2);

    // ---- main stream: G1 (ts) -> attn -> G3 -> bn half 1 ----
    tc_gemm<0><<<dim3(4, 128), 256, SMEM_GEMM>>>(
        (const __nv_bfloat16*)pxh, (const __nv_bfloat16*)pxl, DIN,
        (const __nv_bfloat16*)pB12h, (const __nv_bfloat16*)pB12l,
        (const float*)pbias12, nullptr, DIN, 0);

    attn_kernel<<<N_NODES, 256>>>(nb);

    tc_gemm<1><<<dim3(4, 128), 256, SMEM_GEMM>>>(
        (const __nv_bfloat16*)pch, (const __nv_bfloat16*)pcl, DIN,
        (const __nv_bfloat16*)pB3h, (const __nv_bfloat16*)pB3l,
        (const float*)pb2, nullptr, DIN, 256);

    bn_reduce_kernel<1><<<128, 256>>>();

    // ---- join, finalize, gate ----
    cudaStreamWaitEvent(0, e2, 0);
    bn_finalize_kernel<<<2, 256>>>(gamma, beta);

    tc_gemm<2><<<dim3(8, 128), 256, SMEM_GEMM>>>(
        (const __nv_bfloat16*)poch, (const __nv_bfloat16*)pocl, DCAT,
        (const __nv_bfloat16*)pB4h, (const __nv_bfloat16*)pB4l,
        bg, out, DCAT, 0);
}